// round 2
// baseline (speedup 1.0000x reference)
#include <cuda_runtime.h>
#include <math_constants.h>

#define TT 50
#define TR 48
#define SSTART 48
#define SSTOP 49
#define LL 512
#define BB 1024
#define NTH 64

__device__ __forceinline__ unsigned long long pack2f(float a, float b) {
    unsigned long long u;
    asm("mov.b64 %0, {%1, %2};" : "=l"(u) : "f"(a), "f"(b));
    return u;
}
__device__ __forceinline__ void unpack2f(unsigned long long u, float& a, float& b) {
    asm("mov.b64 {%0, %1}, %2;" : "=f"(a), "=f"(b) : "l"(u));
}
// d = a*b + d, packed 2xf32 (Blackwell FFMA2)
__device__ __forceinline__ void fma2(unsigned long long& d,
                                     unsigned long long a, unsigned long long b) {
    asm("fma.rn.f32x2 %0, %1, %2, %0;" : "+l"(d) : "l"(a), "l"(b));
}

__global__ void zero_out_k(float* o) {
    if (threadIdx.x == 0) o[0] = 0.0f;
}

__global__ __launch_bounds__(NTH) void crf_nll_kernel(
    const float* __restrict__ logits,   // [B, L, T]
    const float* __restrict__ trans,    // [T, T]
    const int*   __restrict__ labels,   // [B, L]
    const int*   __restrict__ lens,     // [B]
    float* __restrict__ out)            // scalar
{
    const int b = blockIdx.x;
    const int j = threadIdx.x;

    __shared__ float tr_s[TT * TT];
    __shared__ __align__(16) float v_s[TR];
    __shared__ float lg_s[TR];
    __shared__ float c_s;
    __shared__ float sum_s[2];

    // transitions -> smem (reused: M init + gold-path scoring)
    for (int k = j; k < TT * TT; k += NTH) tr_s[k] = trans[k];
    __syncthreads();

    const int len = lens[b];
    const float* lrow  = logits + (long)b * (LL * TT);
    const int*  labrow = labels + (long)b * LL;

    // Row j of M = exp(trans[j, :48]) as 24 packed f32x2 regs.
    // Row START = exp(-1e4) = 0 and column STOP = -1e4 contribute exactly 0
    // through exp-underflow (same as the reference's logsumexp), so the two
    // degenerate states are dropped from the recursion entirely.
    unsigned long long M2[TR / 2];
    float trStop = 0.0f;
    if (j < TR) {
        #pragma unroll
        for (int i = 0; i < TR / 2; ++i)
            M2[i] = pack2f(__expf(tr_s[j * TT + 2 * i]),
                           __expf(tr_s[j * TT + 2 * i + 1]));
        trStop = tr_s[SSTOP * TT + j];
    }

    // ---- t = 0: alpha[j] = logit0[j] + trans[j, START]
    float alpha = -CUDART_INF_F;
    float lg0 = 0.0f;
    if (j < TR) {
        lg0 = lrow[j];
        lg_s[j] = lg0;
        alpha = lg0 + tr_s[j * TT + SSTART];
    }
    if (j == 0) c_s = alpha;          // normalizer for step 1
    __syncthreads();

    // gold-path state (thread 0)
    float em = 0.0f, trsc = 0.0f;
    int prev = 0, lbl = 0;
    if (j == 0) {
        prev = labrow[0];
        em   = lg_s[prev];
        trsc = tr_s[prev * TT + SSTART];
    }
    float c  = c_s;
    float lg = (j < TR && 1 < len) ? lrow[TT + j] : 0.0f;
    if (j == 0 && 1 < len) lbl = labrow[1];

    // ---- forward recursion, t = 1 .. len-1
    for (int t = 1; t < len; ++t) {
        // prefetch t+1 (LDG issued early, hidden behind this step)
        float lg2 = (j < TR && (t + 1) < len) ? lrow[(t + 1) * TT + j] : 0.0f;
        int  lblN = (j == 0 && (t + 1) < len) ? labrow[t + 1] : 0;

        if (j < TR) {
            v_s[j]  = __expf(alpha - c);   // c uniform -> exact lse identity
            lg_s[j] = lg;
        }
        __syncthreads();                    // (B) v ready

        if (j < TR) {
            // 48-wide dot as 24 packed FFMA2, 4 independent chains of 6
            const ulonglong2* vv = reinterpret_cast<const ulonglong2*>(v_s);
            unsigned long long a0 = 0ull, a1 = 0ull, a2 = 0ull, a3 = 0ull;
            #pragma unroll
            for (int i = 0; i < TR / 8; ++i) {      // 6 iters of 2 float4s
                ulonglong2 w0 = vv[2 * i];
                ulonglong2 w1 = vv[2 * i + 1];
                fma2(a0, M2[4 * i + 0], w0.x);
                fma2(a1, M2[4 * i + 1], w0.y);
                fma2(a2, M2[4 * i + 2], w1.x);
                fma2(a3, M2[4 * i + 3], w1.y);
            }
            float f0, f1, f2, f3, f4, f5, f6, f7;
            unpack2f(a0, f0, f1); unpack2f(a1, f2, f3);
            unpack2f(a2, f4, f5); unpack2f(a3, f6, f7);
            float S = ((f0 + f1) + (f2 + f3)) + ((f4 + f5) + (f6 + f7));
            alpha = lg + c + __logf(S);
        }
        if (j == 0) {                       // gold-path scores for step t
            em   += lg_s[lbl];
            trsc += tr_s[lbl * TT + prev];
            prev = lbl;
            lbl  = lblN;
            c_s  = alpha;                   // broadcast normalizer for t+1
        }
        __syncthreads();                    // (C) c ready
        c  = c_s;
        lg = lg2;
    }

    // ---- partition = c + log(sum_j exp(alpha[j] + trans[STOP,j] - c))
    float e = (j < TR) ? __expf(alpha + trStop - c) : 0.0f;
    #pragma unroll
    for (int d = 16; d > 0; d >>= 1)
        e += __shfl_xor_sync(0xffffffffu, e, d);
    if ((j & 31) == 0) sum_s[j >> 5] = e;
    __syncthreads();

    if (j == 0) {
        float part = c + __logf(sum_s[0] + sum_s[1]);
        trsc += tr_s[SSTOP * TT + prev];    // closing STOP transition
        atomicAdd(out, (part - em - trsc) * (1.0f / (float)BB));
    }
}

extern "C" void kernel_launch(void* const* d_in, const int* in_sizes, int n_in,
                              void* d_out, int out_size) {
    const float* logits = (const float*)d_in[0];
    const float* trans  = (const float*)d_in[1];
    const int*   labels = (const int*)d_in[2];
    const int*   lens   = (const int*)d_in[3];
    float* out = (float*)d_out;

    zero_out_k<<<1, 32>>>(out);
    crf_nll_kernel<<<BB, NTH>>>(logits, trans, labels, lens, out);
}